// round 1
// baseline (speedup 1.0000x reference)
#include <cuda_runtime.h>

#define NT 256

// Problem constants
// B=256, T=16, O=32, E=32, I=32, H=HL=64, TE=512, EI=64, P=496 (padded to 512)

struct Params {
    const float* z;
    const float *ee1_w,*ee1_b,*ee2_w,*ee2_b,*ee3_w,*ee3_b;
    const float *ne1_w,*ne1_b,*ne2_w,*ne2_b,*ne3_w,*ne3_b,*ne4_w,*ne4_b;
    const float *le1_w,*le1_b,*le2_w,*le2_b,*le3_w,*le3_b;
    const float *lt1_w,*lt1_b,*lt2_w,*lt2_b,*lt3_w,*lt3_b,*lt4_w,*lt4_b,*lt5_w,*lt5_b;
    float* out;
    int t_future;
};

__device__ __forceinline__ void fma4(float acc[4], float a, const float4& w) {
    acc[0] = fmaf(a, w.x, acc[0]);
    acc[1] = fmaf(a, w.y, acc[1]);
    acc[2] = fmaf(a, w.z, acc[2]);
    acc[3] = fmaf(a, w.w, acc[3]);
}

// out[32][64] (optionally +=) = in[32][IN] @ W[IN][64] (+bias) (optional relu)
// Thread tile: 2 rows x 4 cols. 256 threads cover 32x64.
template<int IN, bool ACC, bool RELU>
__device__ __forceinline__ void layer32x64(const float* __restrict__ in,
                                           const float* __restrict__ W,
                                           const float* __restrict__ bias,
                                           float* __restrict__ out, int tid)
{
    const int c0 = (tid & 15) * 4;
    const int r0 = (tid >> 4) * 2;
    float acc0[4], acc1[4];
    if (ACC) {
#pragma unroll
        for (int j = 0; j < 4; j++) {
            acc0[j] = out[r0 * 64 + c0 + j];
            acc1[j] = out[(r0 + 1) * 64 + c0 + j];
        }
    } else {
#pragma unroll
        for (int j = 0; j < 4; j++) {
            float bv = bias ? bias[c0 + j] : 0.f;
            acc0[j] = bv; acc1[j] = bv;
        }
    }
    const float* in0 = in + r0 * IN;
    const float* in1 = in0 + IN;
#pragma unroll 4
    for (int k = 0; k < IN; k += 4) {
        float4 a0 = *(const float4*)(in0 + k);
        float4 a1 = *(const float4*)(in1 + k);
        float4 w0 = *(const float4*)(W + (k + 0) * 64 + c0);
        float4 w1 = *(const float4*)(W + (k + 1) * 64 + c0);
        float4 w2 = *(const float4*)(W + (k + 2) * 64 + c0);
        float4 w3 = *(const float4*)(W + (k + 3) * 64 + c0);
        fma4(acc0, a0.x, w0); fma4(acc0, a0.y, w1); fma4(acc0, a0.z, w2); fma4(acc0, a0.w, w3);
        fma4(acc1, a1.x, w0); fma4(acc1, a1.y, w1); fma4(acc1, a1.z, w2); fma4(acc1, a1.w, w3);
    }
#pragma unroll
    for (int j = 0; j < 4; j++) {
        float v0 = acc0[j], v1 = acc1[j];
        if (RELU) { v0 = fmaxf(v0, 0.f); v1 = fmaxf(v1, 0.f); }
        out[r0 * 64 + c0 + j] = v0;
        out[(r0 + 1) * 64 + c0 + j] = v1;
    }
}

// C[64][64] = relu?(A[64][64] @ Ws[64][64] + bias). A, Ws in shared. 4x4 tiles.
template<bool RELU>
__device__ __forceinline__ void gemm64(const float* __restrict__ A,
                                       const float* __restrict__ Ws,
                                       const float* __restrict__ bias,
                                       float* __restrict__ Cout, int tid)
{
    const int c0 = (tid & 15) * 4;
    const int r0 = (tid >> 4) * 4;
    float acc[4][4];
#pragma unroll
    for (int i = 0; i < 4; i++)
#pragma unroll
        for (int j = 0; j < 4; j++) acc[i][j] = bias[c0 + j];
#pragma unroll 4
    for (int k = 0; k < 64; k += 4) {
        float4 w0 = *(const float4*)(Ws + (k + 0) * 64 + c0);
        float4 w1 = *(const float4*)(Ws + (k + 1) * 64 + c0);
        float4 w2 = *(const float4*)(Ws + (k + 2) * 64 + c0);
        float4 w3 = *(const float4*)(Ws + (k + 3) * 64 + c0);
#pragma unroll
        for (int i = 0; i < 4; i++) {
            float4 a = *(const float4*)(A + (r0 + i) * 64 + k);
            fma4(acc[i], a.x, w0); fma4(acc[i], a.y, w1);
            fma4(acc[i], a.z, w2); fma4(acc[i], a.w, w3);
        }
    }
#pragma unroll
    for (int i = 0; i < 4; i++)
#pragma unroll
        for (int j = 0; j < 4; j++) {
            float v = acc[i][j];
            if (RELU) v = fmaxf(v, 0.f);
            Cout[(r0 + i) * 64 + c0 + j] = v;
        }
}

// G[32][64] += S_chunk[32][64] * H2[64][64]   (S row stride 512)
__device__ __forceinline__ void gemmS(const float* __restrict__ Srow,
                                      const float* __restrict__ H2,
                                      float* __restrict__ G, int tid)
{
    const int k0 = (tid & 15) * 4;
    const int n0 = (tid >> 4) * 2;
    float acc0[4] = {0.f, 0.f, 0.f, 0.f};
    float acc1[4] = {0.f, 0.f, 0.f, 0.f};
#pragma unroll 4
    for (int p = 0; p < 64; p += 4) {
        float4 s0 = *(const float4*)(Srow + n0 * 512 + p);
        float4 s1 = *(const float4*)(Srow + (n0 + 1) * 512 + p);
        float4 h0 = *(const float4*)(H2 + (p + 0) * 64 + k0);
        float4 h1 = *(const float4*)(H2 + (p + 1) * 64 + k0);
        float4 h2v = *(const float4*)(H2 + (p + 2) * 64 + k0);
        float4 h3 = *(const float4*)(H2 + (p + 3) * 64 + k0);
        fma4(acc0, s0.x, h0); fma4(acc0, s0.y, h1); fma4(acc0, s0.z, h2v); fma4(acc0, s0.w, h3);
        fma4(acc1, s1.x, h0); fma4(acc1, s1.y, h1); fma4(acc1, s1.z, h2v); fma4(acc1, s1.w, h3);
    }
#pragma unroll
    for (int j = 0; j < 4; j++) {
        G[n0 * 64 + k0 + j] += acc0[j];
        G[(n0 + 1) * 64 + k0 + j] += acc1[j];
    }
}

// agg[32][64] = G[32][64] @ W3[64][64] + (31-2n)*b3   (scatter bias correction)
__device__ __forceinline__ void aggGemm(const float* __restrict__ G,
                                        const float* __restrict__ W3,
                                        const float* __restrict__ b3,
                                        float* __restrict__ agg, int tid)
{
    const int c0 = (tid & 15) * 4;
    const int r0 = (tid >> 4) * 2;
    const float sc0 = (float)(31 - 2 * r0);
    const float sc1 = (float)(31 - 2 * (r0 + 1));
    float acc0[4], acc1[4];
#pragma unroll
    for (int j = 0; j < 4; j++) {
        float bv = b3[c0 + j];
        acc0[j] = sc0 * bv; acc1[j] = sc1 * bv;
    }
    const float* g0 = G + r0 * 64;
    const float* g1 = g0 + 64;
#pragma unroll 4
    for (int k = 0; k < 64; k += 4) {
        float4 a0 = *(const float4*)(g0 + k);
        float4 a1 = *(const float4*)(g1 + k);
        float4 w0 = *(const float4*)(W3 + (k + 0) * 64 + c0);
        float4 w1 = *(const float4*)(W3 + (k + 1) * 64 + c0);
        float4 w2 = *(const float4*)(W3 + (k + 2) * 64 + c0);
        float4 w3 = *(const float4*)(W3 + (k + 3) * 64 + c0);
        fma4(acc0, a0.x, w0); fma4(acc0, a0.y, w1); fma4(acc0, a0.z, w2); fma4(acc0, a0.w, w3);
        fma4(acc1, a1.x, w0); fma4(acc1, a1.y, w1); fma4(acc1, a1.z, w2); fma4(acc1, a1.w, w3);
    }
#pragma unroll
    for (int j = 0; j < 4; j++) {
        agg[r0 * 64 + c0 + j] = acc0[j];
        agg[(r0 + 1) * 64 + c0 + j] = acc1[j];
    }
}

// small generic layer: out[32][OUT] = relu?(in[32][IN] @ W + b)
__device__ __forceinline__ void layer_small(const float* __restrict__ in, int IN,
                                            const float* __restrict__ W,
                                            const float* __restrict__ bias,
                                            float* __restrict__ out, int OUT,
                                            bool relu, int tid)
{
    for (int idx = tid; idx < 32 * OUT; idx += NT) {
        int r = idx / OUT, c = idx % OUT;
        float acc = bias[c];
        const float* inr = in + r * IN;
#pragma unroll 4
        for (int k = 0; k < IN; k++) acc = fmaf(inr[k], W[k * OUT + c], acc);
        out[idx] = relu ? fmaxf(acc, 0.f) : acc;
    }
}

// full edge block: given ya/yb[32][64], produce agg[32][64]
__device__ __forceinline__ void edge_block(const float* ya, const float* yb,
                                           const float* __restrict__ b1,
                                           const float* w2s, const float* __restrict__ b2,
                                           const float* __restrict__ W3, const float* __restrict__ b3,
                                           float* h1, float* h2, float* G, float* agg,
                                           const float* S,
                                           const unsigned char* ii, const unsigned char* jj,
                                           int tid)
{
    for (int idx = tid; idx < 2048; idx += NT) G[idx] = 0.f;
    __syncthreads();
#pragma unroll 1
    for (int ch = 0; ch < 8; ch++) {
        const int pbase = ch * 64;
        // h1 = relu(ya[ii] + yb[jj] + b1) for this 64-pair chunk
        for (int idx = tid; idx < 64 * 64; idx += NT) {
            int pl = idx >> 6, c = idx & 63;
            int p = pbase + pl;
            float v = ya[ii[p] * 64 + c] + yb[jj[p] * 64 + c] + b1[c];
            h1[idx] = fmaxf(v, 0.f);
        }
        __syncthreads();
        gemm64<true>(h1, w2s, b2, h2, tid);
        __syncthreads();
        gemmS(S + pbase, h2, G, tid);
        __syncthreads();
    }
    aggGemm(G, W3, b3, agg, tid);
    __syncthreads();
}

// smem layout (floats)
#define OFF_SRC   0        // 32*512
#define OFF_S     16384    // 32*512
#define OFF_YA    32768    // 32*64
#define OFF_YB    34816
#define OFF_H1    36864    // 64*64
#define OFF_H2    40960
#define OFF_G     45056    // 32*64
#define OFF_AGG   47104
#define OFF_ZC    49152
#define OFF_W2    51200    // 64*64
#define SMEM_FLOATS 55296
#define SMEM_BYTES  (SMEM_FLOATS * 4 + 1024)   // + ii/jj bytes

__global__ void __launch_bounds__(NT, 1)
RelationalLatentDynamics_82849919140105_kernel(Params P)
{
    extern __shared__ float sm[];
    float* s_src = sm + OFF_SRC;
    float* s_S   = sm + OFF_S;
    float* s_ya  = sm + OFF_YA;
    float* s_yb  = sm + OFF_YB;
    float* s_h1  = sm + OFF_H1;
    float* s_h2  = sm + OFF_H2;
    float* s_g   = sm + OFF_G;
    float* s_agg = sm + OFF_AGG;
    float* s_zc  = sm + OFF_ZC;
    float* s_w2  = sm + OFF_W2;
    unsigned char* s_ii = (unsigned char*)(sm + SMEM_FLOATS);
    unsigned char* s_jj = s_ii + 512;

    const int tid = threadIdx.x;
    const int b = blockIdx.x;

    // pair index tables (padded to 512; pads masked by S=0)
    for (int p = tid; p < 512; p += NT) {
        if (p < 496) {
            int pp = p, i = 0;
            while (pp >= 31 - i) { pp -= 31 - i; i++; }
            s_ii[p] = (unsigned char)i;
            s_jj[p] = (unsigned char)(i + 1 + pp);
        } else {
            s_ii[p] = 0; s_jj[p] = 1;
        }
    }

    // src[o][t*32+e] = t==0 ? z[b,0,o,e] : z[b,t,o,e]-z[b,t-1,o,e]
    const float* zb = P.z + (size_t)b * (16 * 32 * 32);
    for (int idx = tid; idx < 32 * 512; idx += NT) {
        int o = idx >> 9, f = idx & 511;
        int t = f >> 5, e = f & 31;
        float v = zb[(t * 32 + o) * 32 + e];
        if (t > 0) v -= zb[((t - 1) * 32 + o) * 32 + e];
        s_src[o * 512 + f] = v;
    }
    __syncthreads();

    // signed incidence matrix S[32][512]
    for (int idx = tid; idx < 32 * 512; idx += NT) {
        int n = idx >> 9, p = idx & 511;
        float s = 0.f;
        if (p < 496) s = (s_ii[p] == n) ? 1.f : ((s_jj[p] == n) ? -1.f : 0.f);
        s_S[idx] = s;
    }
    // stage ee2_w into smem
    for (int idx = tid; idx < 4096; idx += NT) s_w2[idx] = P.ee2_w[idx];
    __syncthreads();

    // ---- ee edge block ----
    layer32x64<512, false, false>(s_src, P.ee1_w,            nullptr, s_ya, tid);
    layer32x64<512, false, false>(s_src, P.ee1_w + 512 * 64, nullptr, s_yb, tid);
    __syncthreads();
    edge_block(s_ya, s_yb, P.ee1_b, s_w2, P.ee2_b, P.ee3_w, P.ee3_b,
               s_h1, s_h2, s_g, s_agg, s_S, s_ii, s_jj, tid);

    // ---- ne MLP: relu(src@W[0:512] + agg@W[512:576] + b) -> ... -> z_impl ----
    layer32x64<512, false, false>(s_src, P.ne1_w,            P.ne1_b, s_h1, tid);
    layer32x64<64,  true,  true >(s_agg, P.ne1_w + 512 * 64, nullptr, s_h1, tid);
    __syncthreads();
    layer32x64<64, false, true>(s_h1, P.ne2_w, P.ne2_b, s_h2, tid);
    __syncthreads();
    layer_small(s_h2, 64, P.ne3_w, P.ne3_b, s_h1, 32, true, tid);
    __syncthreads();
    layer_small(s_h1, 32, P.ne4_w, P.ne4_b, s_h2, 32, false, tid);  // z_impl [32][32]
    __syncthreads();

    // zc = concat(z[b,-1], z_impl)
    const float* zlast = zb + 15 * 32 * 32;
    for (int idx = tid; idx < 2048; idx += NT) {
        int o = idx >> 6, c = idx & 63;
        s_zc[idx] = (c < 32) ? zlast[o * 32 + c] : s_h2[o * 32 + (c - 32)];
    }
    // stage le2_w; src area is free now -> stage le1_w and lt1_w there
    for (int idx = tid; idx < 4096; idx += NT) s_w2[idx] = P.le2_w[idx];
    float* s_wle1 = s_src;           // 128*64 floats
    float* s_wlt1 = s_src + 8192;    // 128*64 floats
    for (int idx = tid; idx < 8192; idx += NT) {
        s_wle1[idx] = P.le1_w[idx];
        s_wlt1[idx] = P.lt1_w[idx];
    }
    __syncthreads();

    // ---- rollout ----
    float* outb = P.out + (size_t)b * (P.t_future * 32 * 32);
#pragma unroll 1
    for (int t = 0; t < P.t_future; t++) {
        layer32x64<64, false, false>(s_zc, s_wle1,           nullptr, s_ya, tid);
        layer32x64<64, false, false>(s_zc, s_wle1 + 64 * 64, nullptr, s_yb, tid);
        __syncthreads();
        edge_block(s_ya, s_yb, P.le1_b, s_w2, P.le2_b, P.le3_w, P.le3_b,
                   s_h1, s_h2, s_g, s_agg, s_S, s_ii, s_jj, tid);

        // lt MLP: relu(zc@W[0:64] + agg@W[64:128] + b) -> ... -> delta[32][64]
        layer32x64<64, false, false>(s_zc,  s_wlt1,           P.lt1_b, s_h1, tid);
        layer32x64<64, true,  true >(s_agg, s_wlt1 + 64 * 64, nullptr, s_h1, tid);
        __syncthreads();
        layer32x64<64, false, true>(s_h1, P.lt2_w, P.lt2_b, s_h2, tid);
        __syncthreads();
        layer_small(s_h2, 64, P.lt3_w, P.lt3_b, s_h1, 32, true, tid);
        __syncthreads();
        layer_small(s_h1, 32, P.lt4_w, P.lt4_b, s_h2, 16, true, tid);
        __syncthreads();
        layer32x64<16, false, false>(s_h2, P.lt5_w, P.lt5_b, s_g, tid);  // delta
        __syncthreads();

        for (int idx = tid; idx < 2048; idx += NT) {
            float zn = s_zc[idx] + s_g[idx];
            s_zc[idx] = zn;
            int o = idx >> 6, c = idx & 63;
            if (c < 32) outb[t * 1024 + o * 32 + c] = zn;
        }
        __syncthreads();
    }
}

extern "C" void kernel_launch(void* const* d_in, const int* in_sizes, int n_in,
                              void* d_out, int out_size)
{
    Params P;
    int i = 0;
    P.z     = (const float*)d_in[i++];
    P.ee1_w = (const float*)d_in[i++]; P.ee1_b = (const float*)d_in[i++];
    P.ee2_w = (const float*)d_in[i++]; P.ee2_b = (const float*)d_in[i++];
    P.ee3_w = (const float*)d_in[i++]; P.ee3_b = (const float*)d_in[i++];
    P.ne1_w = (const float*)d_in[i++]; P.ne1_b = (const float*)d_in[i++];
    P.ne2_w = (const float*)d_in[i++]; P.ne2_b = (const float*)d_in[i++];
    P.ne3_w = (const float*)d_in[i++]; P.ne3_b = (const float*)d_in[i++];
    P.ne4_w = (const float*)d_in[i++]; P.ne4_b = (const float*)d_in[i++];
    P.le1_w = (const float*)d_in[i++]; P.le1_b = (const float*)d_in[i++];
    P.le2_w = (const float*)d_in[i++]; P.le2_b = (const float*)d_in[i++];
    P.le3_w = (const float*)d_in[i++]; P.le3_b = (const float*)d_in[i++];
    P.lt1_w = (const float*)d_in[i++]; P.lt1_b = (const float*)d_in[i++];
    P.lt2_w = (const float*)d_in[i++]; P.lt2_b = (const float*)d_in[i++];
    P.lt3_w = (const float*)d_in[i++]; P.lt3_b = (const float*)d_in[i++];
    P.lt4_w = (const float*)d_in[i++]; P.lt4_b = (const float*)d_in[i++];
    P.lt5_w = (const float*)d_in[i++]; P.lt5_b = (const float*)d_in[i++];
    P.out = (float*)d_out;
    P.t_future = out_size / (256 * 32 * 32);

    cudaFuncSetAttribute(RelationalLatentDynamics_82849919140105_kernel,
                         cudaFuncAttributeMaxDynamicSharedMemorySize, SMEM_BYTES);
    RelationalLatentDynamics_82849919140105_kernel<<<256, NT, SMEM_BYTES>>>(P);
}

// round 2
// speedup vs baseline: 1.0007x; 1.0007x over previous
#include <cuda_runtime.h>

#define NT 256

// Problem constants
// B=256, T=16, O=32, E=32, I=32, H=HL=64, TE=512, EI=64, P=496 (padded to 512)

struct Params {
    const float* z;
    const float *ee1_w,*ee1_b,*ee2_w,*ee2_b,*ee3_w,*ee3_b;
    const float *ne1_w,*ne1_b,*ne2_w,*ne2_b,*ne3_w,*ne3_b,*ne4_w,*ne4_b;
    const float *le1_w,*le1_b,*le2_w,*le2_b,*le3_w,*le3_b;
    const float *lt1_w,*lt1_b,*lt2_w,*lt2_b,*lt3_w,*lt3_b,*lt4_w,*lt4_b,*lt5_w,*lt5_b;
    float* out;
    int t_future;
};

__device__ __forceinline__ void fma4(float acc[4], float a, const float4& w) {
    acc[0] = fmaf(a, w.x, acc[0]);
    acc[1] = fmaf(a, w.y, acc[1]);
    acc[2] = fmaf(a, w.z, acc[2]);
    acc[3] = fmaf(a, w.w, acc[3]);
}

// out[32][64] (optionally +=) = in[32][IN] @ W[IN][64] (+bias) (optional relu)
// Thread tile: 2 rows x 4 cols. 256 threads cover 32x64.
template<int IN, bool ACC, bool RELU>
__device__ __forceinline__ void layer32x64(const float* __restrict__ in,
                                           const float* __restrict__ W,
                                           const float* __restrict__ bias,
                                           float* __restrict__ out, int tid)
{
    const int c0 = (tid & 15) * 4;
    const int r0 = (tid >> 4) * 2;
    float acc0[4], acc1[4];
    if (ACC) {
#pragma unroll
        for (int j = 0; j < 4; j++) {
            acc0[j] = out[r0 * 64 + c0 + j];
            acc1[j] = out[(r0 + 1) * 64 + c0 + j];
        }
    } else {
#pragma unroll
        for (int j = 0; j < 4; j++) {
            float bv = bias ? bias[c0 + j] : 0.f;
            acc0[j] = bv; acc1[j] = bv;
        }
    }
    const float* in0 = in + r0 * IN;
    const float* in1 = in0 + IN;
#pragma unroll 4
    for (int k = 0; k < IN; k += 4) {
        float4 a0 = *(const float4*)(in0 + k);
        float4 a1 = *(const float4*)(in1 + k);
        float4 w0 = *(const float4*)(W + (k + 0) * 64 + c0);
        float4 w1 = *(const float4*)(W + (k + 1) * 64 + c0);
        float4 w2 = *(const float4*)(W + (k + 2) * 64 + c0);
        float4 w3 = *(const float4*)(W + (k + 3) * 64 + c0);
        fma4(acc0, a0.x, w0); fma4(acc0, a0.y, w1); fma4(acc0, a0.z, w2); fma4(acc0, a0.w, w3);
        fma4(acc1, a1.x, w0); fma4(acc1, a1.y, w1); fma4(acc1, a1.z, w2); fma4(acc1, a1.w, w3);
    }
#pragma unroll
    for (int j = 0; j < 4; j++) {
        float v0 = acc0[j], v1 = acc1[j];
        if (RELU) { v0 = fmaxf(v0, 0.f); v1 = fmaxf(v1, 0.f); }
        out[r0 * 64 + c0 + j] = v0;
        out[(r0 + 1) * 64 + c0 + j] = v1;
    }
}

// C[64][64] = relu?(A[64][64] @ Ws[64][64] + bias). A, Ws in shared. 4x4 tiles.
template<bool RELU>
__device__ __forceinline__ void gemm64(const float* __restrict__ A,
                                       const float* __restrict__ Ws,
                                       const float* __restrict__ bias,
                                       float* __restrict__ Cout, int tid)
{
    const int c0 = (tid & 15) * 4;
    const int r0 = (tid >> 4) * 4;
    float acc[4][4];
#pragma unroll
    for (int i = 0; i < 4; i++)
#pragma unroll
        for (int j = 0; j < 4; j++) acc[i][j] = bias[c0 + j];
#pragma unroll 4
    for (int k = 0; k < 64; k += 4) {
        float4 w0 = *(const float4*)(Ws + (k + 0) * 64 + c0);
        float4 w1 = *(const float4*)(Ws + (k + 1) * 64 + c0);
        float4 w2 = *(const float4*)(Ws + (k + 2) * 64 + c0);
        float4 w3 = *(const float4*)(Ws + (k + 3) * 64 + c0);
#pragma unroll
        for (int i = 0; i < 4; i++) {
            float4 a = *(const float4*)(A + (r0 + i) * 64 + k);
            fma4(acc[i], a.x, w0); fma4(acc[i], a.y, w1);
            fma4(acc[i], a.z, w2); fma4(acc[i], a.w, w3);
        }
    }
#pragma unroll
    for (int i = 0; i < 4; i++)
#pragma unroll
        for (int j = 0; j < 4; j++) {
            float v = acc[i][j];
            if (RELU) v = fmaxf(v, 0.f);
            Cout[(r0 + i) * 64 + c0 + j] = v;
        }
}

// G[32][64] += S_chunk[32][64] * H2[64][64]   (S row stride 512)
__device__ __forceinline__ void gemmS(const float* __restrict__ Srow,
                                      const float* __restrict__ H2,
                                      float* __restrict__ G, int tid)
{
    const int k0 = (tid & 15) * 4;
    const int n0 = (tid >> 4) * 2;
    float acc0[4] = {0.f, 0.f, 0.f, 0.f};
    float acc1[4] = {0.f, 0.f, 0.f, 0.f};
#pragma unroll 4
    for (int p = 0; p < 64; p += 4) {
        float4 s0 = *(const float4*)(Srow + n0 * 512 + p);
        float4 s1 = *(const float4*)(Srow + (n0 + 1) * 512 + p);
        float4 h0 = *(const float4*)(H2 + (p + 0) * 64 + k0);
        float4 h1 = *(const float4*)(H2 + (p + 1) * 64 + k0);
        float4 h2v = *(const float4*)(H2 + (p + 2) * 64 + k0);
        float4 h3 = *(const float4*)(H2 + (p + 3) * 64 + k0);
        fma4(acc0, s0.x, h0); fma4(acc0, s0.y, h1); fma4(acc0, s0.z, h2v); fma4(acc0, s0.w, h3);
        fma4(acc1, s1.x, h0); fma4(acc1, s1.y, h1); fma4(acc1, s1.z, h2v); fma4(acc1, s1.w, h3);
    }
#pragma unroll
    for (int j = 0; j < 4; j++) {
        G[n0 * 64 + k0 + j] += acc0[j];
        G[(n0 + 1) * 64 + k0 + j] += acc1[j];
    }
}

// agg[32][64] = G[32][64] @ W3[64][64] + (31-2n)*b3   (scatter bias correction)
__device__ __forceinline__ void aggGemm(const float* __restrict__ G,
                                        const float* __restrict__ W3,
                                        const float* __restrict__ b3,
                                        float* __restrict__ agg, int tid)
{
    const int c0 = (tid & 15) * 4;
    const int r0 = (tid >> 4) * 2;
    const float sc0 = (float)(31 - 2 * r0);
    const float sc1 = (float)(31 - 2 * (r0 + 1));
    float acc0[4], acc1[4];
#pragma unroll
    for (int j = 0; j < 4; j++) {
        float bv = b3[c0 + j];
        acc0[j] = sc0 * bv; acc1[j] = sc1 * bv;
    }
    const float* g0 = G + r0 * 64;
    const float* g1 = g0 + 64;
#pragma unroll 4
    for (int k = 0; k < 64; k += 4) {
        float4 a0 = *(const float4*)(g0 + k);
        float4 a1 = *(const float4*)(g1 + k);
        float4 w0 = *(const float4*)(W3 + (k + 0) * 64 + c0);
        float4 w1 = *(const float4*)(W3 + (k + 1) * 64 + c0);
        float4 w2 = *(const float4*)(W3 + (k + 2) * 64 + c0);
        float4 w3 = *(const float4*)(W3 + (k + 3) * 64 + c0);
        fma4(acc0, a0.x, w0); fma4(acc0, a0.y, w1); fma4(acc0, a0.z, w2); fma4(acc0, a0.w, w3);
        fma4(acc1, a1.x, w0); fma4(acc1, a1.y, w1); fma4(acc1, a1.z, w2); fma4(acc1, a1.w, w3);
    }
#pragma unroll
    for (int j = 0; j < 4; j++) {
        agg[r0 * 64 + c0 + j] = acc0[j];
        agg[(r0 + 1) * 64 + c0 + j] = acc1[j];
    }
}

// small generic layer: out[32][OUT] = relu?(in[32][IN] @ W + b)
__device__ __forceinline__ void layer_small(const float* __restrict__ in, int IN,
                                            const float* __restrict__ W,
                                            const float* __restrict__ bias,
                                            float* __restrict__ out, int OUT,
                                            bool relu, int tid)
{
    for (int idx = tid; idx < 32 * OUT; idx += NT) {
        int r = idx / OUT, c = idx % OUT;
        float acc = bias[c];
        const float* inr = in + r * IN;
#pragma unroll 4
        for (int k = 0; k < IN; k++) acc = fmaf(inr[k], W[k * OUT + c], acc);
        out[idx] = relu ? fmaxf(acc, 0.f) : acc;
    }
}

// full edge block: given ya/yb[32][64], produce agg[32][64]
__device__ __forceinline__ void edge_block(const float* ya, const float* yb,
                                           const float* __restrict__ b1,
                                           const float* w2s, const float* __restrict__ b2,
                                           const float* __restrict__ W3, const float* __restrict__ b3,
                                           float* h1, float* h2, float* G, float* agg,
                                           const float* S,
                                           const unsigned char* ii, const unsigned char* jj,
                                           int tid)
{
    for (int idx = tid; idx < 2048; idx += NT) G[idx] = 0.f;
    __syncthreads();
#pragma unroll 1
    for (int ch = 0; ch < 8; ch++) {
        const int pbase = ch * 64;
        // h1 = relu(ya[ii] + yb[jj] + b1) for this 64-pair chunk
        for (int idx = tid; idx < 64 * 64; idx += NT) {
            int pl = idx >> 6, c = idx & 63;
            int p = pbase + pl;
            float v = ya[ii[p] * 64 + c] + yb[jj[p] * 64 + c] + b1[c];
            h1[idx] = fmaxf(v, 0.f);
        }
        __syncthreads();
        gemm64<true>(h1, w2s, b2, h2, tid);
        __syncthreads();
        gemmS(S + pbase, h2, G, tid);
        __syncthreads();
    }
    aggGemm(G, W3, b3, agg, tid);
    __syncthreads();
}

// smem layout (floats)
#define OFF_SRC   0        // 32*512
#define OFF_S     16384    // 32*512
#define OFF_YA    32768    // 32*64
#define OFF_YB    34816
#define OFF_H1    36864    // 64*64
#define OFF_H2    40960
#define OFF_G     45056    // 32*64
#define OFF_AGG   47104
#define OFF_ZC    49152
#define OFF_W2    51200    // 64*64
#define SMEM_FLOATS 55296
#define SMEM_BYTES  (SMEM_FLOATS * 4 + 1024)   // + ii/jj bytes

__global__ void __launch_bounds__(NT, 1)
RelationalLatentDynamics_82849919140105_kernel(Params P)
{
    extern __shared__ float sm[];
    float* s_src = sm + OFF_SRC;
    float* s_S   = sm + OFF_S;
    float* s_ya  = sm + OFF_YA;
    float* s_yb  = sm + OFF_YB;
    float* s_h1  = sm + OFF_H1;
    float* s_h2  = sm + OFF_H2;
    float* s_g   = sm + OFF_G;
    float* s_agg = sm + OFF_AGG;
    float* s_zc  = sm + OFF_ZC;
    float* s_w2  = sm + OFF_W2;
    unsigned char* s_ii = (unsigned char*)(sm + SMEM_FLOATS);
    unsigned char* s_jj = s_ii + 512;

    const int tid = threadIdx.x;
    const int b = blockIdx.x;

    // pair index tables (padded to 512; pads masked by S=0)
    for (int p = tid; p < 512; p += NT) {
        if (p < 496) {
            int pp = p, i = 0;
            while (pp >= 31 - i) { pp -= 31 - i; i++; }
            s_ii[p] = (unsigned char)i;
            s_jj[p] = (unsigned char)(i + 1 + pp);
        } else {
            s_ii[p] = 0; s_jj[p] = 1;
        }
    }

    // src[o][t*32+e] = t==0 ? z[b,0,o,e] : z[b,t,o,e]-z[b,t-1,o,e]
    const float* zb = P.z + (size_t)b * (16 * 32 * 32);
    for (int idx = tid; idx < 32 * 512; idx += NT) {
        int o = idx >> 9, f = idx & 511;
        int t = f >> 5, e = f & 31;
        float v = zb[(t * 32 + o) * 32 + e];
        if (t > 0) v -= zb[((t - 1) * 32 + o) * 32 + e];
        s_src[o * 512 + f] = v;
    }
    __syncthreads();

    // signed incidence matrix S[32][512]
    for (int idx = tid; idx < 32 * 512; idx += NT) {
        int n = idx >> 9, p = idx & 511;
        float s = 0.f;
        if (p < 496) s = (s_ii[p] == n) ? 1.f : ((s_jj[p] == n) ? -1.f : 0.f);
        s_S[idx] = s;
    }
    // stage ee2_w into smem
    for (int idx = tid; idx < 4096; idx += NT) s_w2[idx] = P.ee2_w[idx];
    __syncthreads();

    // ---- ee edge block ----
    layer32x64<512, false, false>(s_src, P.ee1_w,            nullptr, s_ya, tid);
    layer32x64<512, false, false>(s_src, P.ee1_w + 512 * 64, nullptr, s_yb, tid);
    __syncthreads();
    edge_block(s_ya, s_yb, P.ee1_b, s_w2, P.ee2_b, P.ee3_w, P.ee3_b,
               s_h1, s_h2, s_g, s_agg, s_S, s_ii, s_jj, tid);

    // ---- ne MLP: relu(src@W[0:512] + agg@W[512:576] + b) -> ... -> z_impl ----
    layer32x64<512, false, false>(s_src, P.ne1_w,            P.ne1_b, s_h1, tid);
    layer32x64<64,  true,  true >(s_agg, P.ne1_w + 512 * 64, nullptr, s_h1, tid);
    __syncthreads();
    layer32x64<64, false, true>(s_h1, P.ne2_w, P.ne2_b, s_h2, tid);
    __syncthreads();
    layer_small(s_h2, 64, P.ne3_w, P.ne3_b, s_h1, 32, true, tid);
    __syncthreads();
    layer_small(s_h1, 32, P.ne4_w, P.ne4_b, s_h2, 32, false, tid);  // z_impl [32][32]
    __syncthreads();

    // zc = concat(z[b,-1], z_impl)
    const float* zlast = zb + 15 * 32 * 32;
    for (int idx = tid; idx < 2048; idx += NT) {
        int o = idx >> 6, c = idx & 63;
        s_zc[idx] = (c < 32) ? zlast[o * 32 + c] : s_h2[o * 32 + (c - 32)];
    }
    // stage le2_w; src area is free now -> stage le1_w and lt1_w there
    for (int idx = tid; idx < 4096; idx += NT) s_w2[idx] = P.le2_w[idx];
    float* s_wle1 = s_src;           // 128*64 floats
    float* s_wlt1 = s_src + 8192;    // 128*64 floats
    for (int idx = tid; idx < 8192; idx += NT) {
        s_wle1[idx] = P.le1_w[idx];
        s_wlt1[idx] = P.lt1_w[idx];
    }
    __syncthreads();

    // ---- rollout ----
    float* outb = P.out + (size_t)b * (P.t_future * 32 * 32);
#pragma unroll 1
    for (int t = 0; t < P.t_future; t++) {
        layer32x64<64, false, false>(s_zc, s_wle1,           nullptr, s_ya, tid);
        layer32x64<64, false, false>(s_zc, s_wle1 + 64 * 64, nullptr, s_yb, tid);
        __syncthreads();
        edge_block(s_ya, s_yb, P.le1_b, s_w2, P.le2_b, P.le3_w, P.le3_b,
                   s_h1, s_h2, s_g, s_agg, s_S, s_ii, s_jj, tid);

        // lt MLP: relu(zc@W[0:64] + agg@W[64:128] + b) -> ... -> delta[32][64]
        layer32x64<64, false, false>(s_zc,  s_wlt1,           P.lt1_b, s_h1, tid);
        layer32x64<64, true,  true >(s_agg, s_wlt1 + 64 * 64, nullptr, s_h1, tid);
        __syncthreads();
        layer32x64<64, false, true>(s_h1, P.lt2_w, P.lt2_b, s_h2, tid);
        __syncthreads();
        layer_small(s_h2, 64, P.lt3_w, P.lt3_b, s_h1, 32, true, tid);
        __syncthreads();
        layer_small(s_h1, 32, P.lt4_w, P.lt4_b, s_h2, 16, true, tid);
        __syncthreads();
        layer32x64<16, false, false>(s_h2, P.lt5_w, P.lt5_b, s_g, tid);  // delta
        __syncthreads();

        for (int idx = tid; idx < 2048; idx += NT) {
            float zn = s_zc[idx] + s_g[idx];
            s_zc[idx] = zn;
            int o = idx >> 6, c = idx & 63;
            if (c < 32) outb[t * 1024 + o * 32 + c] = zn;
        }
        __syncthreads();
    }
}

extern "C" void kernel_launch(void* const* d_in, const int* in_sizes, int n_in,
                              void* d_out, int out_size)
{
    Params P;
    int i = 0;
    P.z     = (const float*)d_in[i++];
    P.ee1_w = (const float*)d_in[i++]; P.ee1_b = (const float*)d_in[i++];
    P.ee2_w = (const float*)d_in[i++]; P.ee2_b = (const float*)d_in[i++];
    P.ee3_w = (const float*)d_in[i++]; P.ee3_b = (const float*)d_in[i++];
    P.ne1_w = (const float*)d_in[i++]; P.ne1_b = (const float*)d_in[i++];
    P.ne2_w = (const float*)d_in[i++]; P.ne2_b = (const float*)d_in[i++];
    P.ne3_w = (const float*)d_in[i++]; P.ne3_b = (const float*)d_in[i++];
    P.ne4_w = (const float*)d_in[i++]; P.ne4_b = (const float*)d_in[i++];
    P.le1_w = (const float*)d_in[i++]; P.le1_b = (const float*)d_in[i++];
    P.le2_w = (const float*)d_in[i++]; P.le2_b = (const float*)d_in[i++];
    P.le3_w = (const float*)d_in[i++]; P.le3_b = (const float*)d_in[i++];
    P.lt1_w = (const float*)d_in[i++]; P.lt1_b = (const float*)d_in[i++];
    P.lt2_w = (const float*)d_in[i++]; P.lt2_b = (const float*)d_in[i++];
    P.lt3_w = (const float*)d_in[i++]; P.lt3_b = (const float*)d_in[i++];
    P.lt4_w = (const float*)d_in[i++]; P.lt4_b = (const float*)d_in[i++];
    P.lt5_w = (const float*)d_in[i++]; P.lt5_b = (const float*)d_in[i++];
    P.out = (float*)d_out;
    P.t_future = out_size / (256 * 32 * 32);

    cudaFuncSetAttribute(RelationalLatentDynamics_82849919140105_kernel,
                         cudaFuncAttributeMaxDynamicSharedMemorySize, SMEM_BYTES);
    RelationalLatentDynamics_82849919140105_kernel<<<256, NT, SMEM_BYTES>>>(P);
}

// round 3
// speedup vs baseline: 1.5200x; 1.5189x over previous
#include <cuda_runtime.h>

#define NT 256

// Problem constants: B=256, T=16, O=32, E=32, I=32, H=HL=64, TE=512, EI=64, P=496

struct Params {
    const float* z;
    const float *ee1_w,*ee1_b,*ee2_w,*ee2_b,*ee3_w,*ee3_b;
    const float *ne1_w,*ne1_b,*ne2_w,*ne2_b,*ne3_w,*ne3_b,*ne4_w,*ne4_b;
    const float *le1_w,*le1_b,*le2_w,*le2_b,*le3_w,*le3_b;
    const float *lt1_w,*lt1_b,*lt2_w,*lt2_b,*lt3_w,*lt3_b,*lt4_w,*lt4_b,*lt5_w,*lt5_b;
    float* out;
    int t_future;
};

__device__ __forceinline__ void fma4(float acc[4], float a, const float4& w) {
    acc[0] = fmaf(a, w.x, acc[0]);
    acc[1] = fmaf(a, w.y, acc[1]);
    acc[2] = fmaf(a, w.z, acc[2]);
    acc[3] = fmaf(a, w.w, acc[3]);
}

// out[32][64] (optionally +=) = in[32][IN] @ W[IN][64] (+bias) (optional relu)
template<int IN, bool ACC, bool RELU>
__device__ __forceinline__ void layer32x64(const float* __restrict__ in,
                                           const float* __restrict__ W,
                                           const float* __restrict__ bias,
                                           float* __restrict__ out, int tid)
{
    const int c0 = (tid & 15) * 4;
    const int r0 = (tid >> 4) * 2;
    float acc0[4], acc1[4];
    if (ACC) {
#pragma unroll
        for (int j = 0; j < 4; j++) {
            acc0[j] = out[r0 * 64 + c0 + j];
            acc1[j] = out[(r0 + 1) * 64 + c0 + j];
        }
    } else {
#pragma unroll
        for (int j = 0; j < 4; j++) {
            float bv = bias ? bias[c0 + j] : 0.f;
            acc0[j] = bv; acc1[j] = bv;
        }
    }
    const float* in0 = in + r0 * IN;
    const float* in1 = in0 + IN;
#pragma unroll 4
    for (int k = 0; k < IN; k += 4) {
        float4 a0 = *(const float4*)(in0 + k);
        float4 a1 = *(const float4*)(in1 + k);
        float4 w0 = *(const float4*)(W + (k + 0) * 64 + c0);
        float4 w1 = *(const float4*)(W + (k + 1) * 64 + c0);
        float4 w2 = *(const float4*)(W + (k + 2) * 64 + c0);
        float4 w3 = *(const float4*)(W + (k + 3) * 64 + c0);
        fma4(acc0, a0.x, w0); fma4(acc0, a0.y, w1); fma4(acc0, a0.z, w2); fma4(acc0, a0.w, w3);
        fma4(acc1, a1.x, w0); fma4(acc1, a1.y, w1); fma4(acc1, a1.z, w2); fma4(acc1, a1.w, w3);
    }
#pragma unroll
    for (int j = 0; j < 4; j++) {
        float v0 = acc0[j], v1 = acc1[j];
        if (RELU) { v0 = fmaxf(v0, 0.f); v1 = fmaxf(v1, 0.f); }
        out[r0 * 64 + c0 + j] = v0;
        out[(r0 + 1) * 64 + c0 + j] = v1;
    }
}

// C[64][64] (stride OS) = relu(A[64][64] @ Ws[64][64] + bias). A, Ws in shared.
template<int OS>
__device__ __forceinline__ void gemm64s(const float* __restrict__ A,
                                        const float* __restrict__ Ws,
                                        const float* __restrict__ bias,
                                        float* __restrict__ Cout, int tid)
{
    const int c0 = (tid & 15) * 4;
    const int r0 = (tid >> 4) * 4;
    float acc[4][4];
#pragma unroll
    for (int i = 0; i < 4; i++)
#pragma unroll
        for (int j = 0; j < 4; j++) acc[i][j] = bias[c0 + j];
#pragma unroll 4
    for (int k = 0; k < 64; k += 4) {
        float4 w0 = *(const float4*)(Ws + (k + 0) * 64 + c0);
        float4 w1 = *(const float4*)(Ws + (k + 1) * 64 + c0);
        float4 w2 = *(const float4*)(Ws + (k + 2) * 64 + c0);
        float4 w3 = *(const float4*)(Ws + (k + 3) * 64 + c0);
#pragma unroll
        for (int i = 0; i < 4; i++) {
            float4 a = *(const float4*)(A + (r0 + i) * 64 + k);
            fma4(acc[i], a.x, w0); fma4(acc[i], a.y, w1);
            fma4(acc[i], a.z, w2); fma4(acc[i], a.w, w3);
        }
    }
#pragma unroll
    for (int i = 0; i < 4; i++)
#pragma unroll
        for (int j = 0; j < 4; j++)
            Cout[(r0 + i) * OS + c0 + j] = fmaxf(acc[i][j], 0.f);
}

// agg[32][64] = G[32][64] @ W3[64][64] + (31-2n)*b3   (scatter bias correction)
__device__ __forceinline__ void aggGemm(const float* __restrict__ G,
                                        const float* __restrict__ W3,
                                        const float* __restrict__ b3,
                                        float* __restrict__ agg, int tid)
{
    const int c0 = (tid & 15) * 4;
    const int r0 = (tid >> 4) * 2;
    const float sc0 = (float)(31 - 2 * r0);
    const float sc1 = (float)(31 - 2 * (r0 + 1));
    float acc0[4], acc1[4];
#pragma unroll
    for (int j = 0; j < 4; j++) {
        float bv = b3[c0 + j];
        acc0[j] = sc0 * bv; acc1[j] = sc1 * bv;
    }
    const float* g0 = G + r0 * 64;
    const float* g1 = g0 + 64;
#pragma unroll 4
    for (int k = 0; k < 64; k += 4) {
        float4 a0 = *(const float4*)(g0 + k);
        float4 a1 = *(const float4*)(g1 + k);
        float4 w0 = *(const float4*)(W3 + (k + 0) * 64 + c0);
        float4 w1 = *(const float4*)(W3 + (k + 1) * 64 + c0);
        float4 w2 = *(const float4*)(W3 + (k + 2) * 64 + c0);
        float4 w3 = *(const float4*)(W3 + (k + 3) * 64 + c0);
        fma4(acc0, a0.x, w0); fma4(acc0, a0.y, w1); fma4(acc0, a0.z, w2); fma4(acc0, a0.w, w3);
        fma4(acc1, a1.x, w0); fma4(acc1, a1.y, w1); fma4(acc1, a1.z, w2); fma4(acc1, a1.w, w3);
    }
#pragma unroll
    for (int j = 0; j < 4; j++) {
        agg[r0 * 64 + c0 + j] = acc0[j];
        agg[(r0 + 1) * 64 + c0 + j] = acc1[j];
    }
}

// small generic layer: out[32][OUT] = relu?(in[32][IN] @ W + b)
__device__ __forceinline__ void layer_small(const float* __restrict__ in, int IN,
                                            const float* __restrict__ W,
                                            const float* __restrict__ bias,
                                            float* __restrict__ out, int OUT,
                                            bool relu, int tid)
{
    for (int idx = tid; idx < 32 * OUT; idx += NT) {
        int r = idx / OUT, c = idx % OUT;
        float acc = bias[c];
        const float* inr = in + r * IN;
#pragma unroll 4
        for (int k = 0; k < IN; k++) acc = fmaf(inr[k], W[k * OUT + c], acc);
        out[idx] = relu ? fmaxf(acc, 0.f) : acc;
    }
}

// accumulate one 64-k chunk: acc[2][4] += src[32][64] @ Wg[64][64] (Wg global)
__device__ __forceinline__ void acc_chunk(const float* __restrict__ src,
                                          const float* __restrict__ Wg,
                                          float acc0[4], float acc1[4],
                                          int r0, int c0)
{
    const float* in0 = src + r0 * 64;
    const float* in1 = in0 + 64;
#pragma unroll 4
    for (int k = 0; k < 64; k += 4) {
        float4 a0 = *(const float4*)(in0 + k);
        float4 a1 = *(const float4*)(in1 + k);
        float4 w0 = *(const float4*)(Wg + (k + 0) * 64 + c0);
        float4 w1 = *(const float4*)(Wg + (k + 1) * 64 + c0);
        float4 w2 = *(const float4*)(Wg + (k + 2) * 64 + c0);
        float4 w3 = *(const float4*)(Wg + (k + 3) * 64 + c0);
        fma4(acc0, a0.x, w0); fma4(acc0, a0.y, w1); fma4(acc0, a0.z, w2); fma4(acc0, a0.w, w3);
        fma4(acc1, a1.x, w0); fma4(acc1, a1.y, w1); fma4(acc1, a1.z, w2); fma4(acc1, a1.w, w3);
    }
}

#define H2S 68   // padded stride for h2 (bank-conflict-free scatter)

// edge block: given ya/yb[32][64] in smem, produce agg[32][64].
// Sparse signed scatter replaces the dense S-GEMM; per-thread G in registers.
__device__ __forceinline__ void edge_block(const float* ya, const float* yb,
                                           const float* __restrict__ b1,
                                           const float* w2s, const float* __restrict__ b2,
                                           const float* w3s, const float* __restrict__ b3,
                                           float* h1, float* h2, float* Gs, float* agg,
                                           const unsigned char* ii, const unsigned char* jj,
                                           const unsigned short* jl,
                                           int tid)
{
    const int n   = tid >> 3;
    const int c0s = (tid & 7) * 8;
    const int rs    = n * 31 - ((n * (n - 1)) >> 1);  // first pair with ii==n
    const int iiend = rs + 31 - n;
    float g[8];
#pragma unroll
    for (int j = 0; j < 8; j++) g[j] = 0.f;
    int kcur = 0;

#pragma unroll 1
    for (int ch = 0; ch < 8; ch++) {
        const int p0 = ch * 64;
        // h1 = relu(ya[ii] + yb[jj] + b1) for this 64-pair chunk
        for (int idx = tid; idx < 64 * 64; idx += NT) {
            int pl = idx >> 6, c = idx & 63;
            int p = p0 + pl;
            float v = ya[ii[p] * 64 + c] + yb[jj[p] * 64 + c] + b1[c];
            h1[idx] = fmaxf(v, 0.f);
        }
        __syncthreads();
        gemm64s<H2S>(h1, w2s, b2, h2, tid);
        __syncthreads();
        // signed sparse scatter into register G
        int lo = max(rs, p0), hi = min(iiend, p0 + 64);
        for (int p = lo; p < hi; p++) {
            const float* r = h2 + (p - p0) * H2S + c0s;
            float4 v0 = *(const float4*)(r);
            float4 v1 = *(const float4*)(r + 4);
            g[0] += v0.x; g[1] += v0.y; g[2] += v0.z; g[3] += v0.w;
            g[4] += v1.x; g[5] += v1.y; g[6] += v1.z; g[7] += v1.w;
        }
        while (kcur < n) {
            int p = jl[(n << 5) + kcur];
            if (p >= p0 + 64) break;
            const float* r = h2 + (p - p0) * H2S + c0s;
            float4 v0 = *(const float4*)(r);
            float4 v1 = *(const float4*)(r + 4);
            g[0] -= v0.x; g[1] -= v0.y; g[2] -= v0.z; g[3] -= v0.w;
            g[4] -= v1.x; g[5] -= v1.y; g[6] -= v1.z; g[7] -= v1.w;
            kcur++;
        }
    }
#pragma unroll
    for (int j = 0; j < 8; j++) Gs[n * 64 + c0s + j] = g[j];
    __syncthreads();
    aggGemm(Gs, w3s, b3, agg, tid);
    __syncthreads();
}

// smem layout (float offsets)
#define OFF_H1   0       // 64*64
#define OFF_H2   4096    // 64*68
#define OFF_YA   8448    // 32*64
#define OFF_YB   10496
#define OFF_AGG  12544
#define OFF_ZC   14592
#define OFF_W2   16640   // 64*64
#define OFF_W3   20736   // 64*64
#define SMEM_FLOATS 24832
#define SMEM_BYTES  (SMEM_FLOATS * 4 + 2048 + 1024)  // + jl(u16 x1024) + ii/jj

__global__ void __launch_bounds__(NT, 2)
RelationalLatentDynamics_82849919140105_kernel(Params P)
{
    extern __shared__ float sm[];
    float* s_h1  = sm + OFF_H1;
    float* s_h2  = sm + OFF_H2;
    float* s_ya  = sm + OFF_YA;
    float* s_yb  = sm + OFF_YB;
    float* s_agg = sm + OFF_AGG;
    float* s_zc  = sm + OFF_ZC;
    float* s_w2  = sm + OFF_W2;
    float* s_w3  = sm + OFF_W3;
    unsigned short* s_jl = (unsigned short*)(sm + SMEM_FLOATS);
    unsigned char*  s_ii = (unsigned char*)(s_jl + 1024);
    unsigned char*  s_jj = s_ii + 512;

    const int tid = threadIdx.x;
    const int b = blockIdx.x;
    const int c0 = (tid & 15) * 4;
    const int r0 = (tid >> 4) * 2;

    // pair index tables (padded to 512)
    for (int p = tid; p < 512; p += NT) {
        if (p < 496) {
            int pp = p, i = 0;
            while (pp >= 31 - i) { pp -= 31 - i; i++; }
            s_ii[p] = (unsigned char)i;
            s_jj[p] = (unsigned char)(i + 1 + pp);
        } else {
            s_ii[p] = 0; s_jj[p] = 1;
        }
    }
    // jl[n][k] = index of pair (k, n) for k < n
    for (int idx = tid; idx < 1024; idx += NT) {
        int n = idx >> 5, k = idx & 31;
        s_jl[idx] = (k < n)
            ? (unsigned short)(k * 31 - ((k * (k - 1)) >> 1) + (n - k - 1))
            : (unsigned short)0xFFFF;
    }

    const float* zb = P.z + (size_t)b * (16 * 32 * 32);

    // ---- Phase A: ya/yb = src @ ee1_w (streamed src chunks, register acc) ----
    {
        float accA0[4] = {0,0,0,0}, accA1[4] = {0,0,0,0};
        float accB0[4] = {0,0,0,0}, accB1[4] = {0,0,0,0};
#pragma unroll 1
        for (int ch = 0; ch < 8; ch++) {
            for (int idx = tid; idx < 2048; idx += NT) {
                int o = idx >> 6, fl = idx & 63;
                int t = 2 * ch + (fl >> 5), e = fl & 31;
                float v = zb[(t * 32 + o) * 32 + e];
                if (t > 0) v -= zb[((t - 1) * 32 + o) * 32 + e];
                s_h1[o * 64 + fl] = v;
            }
            __syncthreads();
            acc_chunk(s_h1, P.ee1_w + ch * 4096, accA0, accA1, r0, c0);
            acc_chunk(s_h1, P.ee1_w + 512 * 64 + ch * 4096, accB0, accB1, r0, c0);
            __syncthreads();
        }
#pragma unroll
        for (int j = 0; j < 4; j++) {
            s_ya[r0 * 64 + c0 + j] = accA0[j];
            s_ya[(r0 + 1) * 64 + c0 + j] = accA1[j];
            s_yb[r0 * 64 + c0 + j] = accB0[j];
            s_yb[(r0 + 1) * 64 + c0 + j] = accB1[j];
        }
    }
    // stage ee2_w / ee3_w
    for (int idx = tid; idx < 4096; idx += NT) {
        s_w2[idx] = P.ee2_w[idx];
        s_w3[idx] = P.ee3_w[idx];
    }
    __syncthreads();

    // ---- ee edge block ----
    edge_block(s_ya, s_yb, P.ee1_b, s_w2, P.ee2_b, s_w3, P.ee3_b,
               s_h1, s_h2, s_yb, s_agg, s_ii, s_jj, s_jl, tid);

    // ---- ne MLP ----
    // agg part of layer 1 (with bias), then stream src chunks for the 512-K part
    layer32x64<64, false, false>(s_agg, P.ne1_w + 512 * 64, P.ne1_b, s_ya, tid);
    {
        float acc0[4], acc1[4];
#pragma unroll
        for (int j = 0; j < 4; j++) {
            acc0[j] = s_ya[r0 * 64 + c0 + j];           // own cells, no sync needed
            acc1[j] = s_ya[(r0 + 1) * 64 + c0 + j];
        }
#pragma unroll 1
        for (int ch = 0; ch < 8; ch++) {
            for (int idx = tid; idx < 2048; idx += NT) {
                int o = idx >> 6, fl = idx & 63;
                int t = 2 * ch + (fl >> 5), e = fl & 31;
                float v = zb[(t * 32 + o) * 32 + e];
                if (t > 0) v -= zb[((t - 1) * 32 + o) * 32 + e];
                s_h1[o * 64 + fl] = v;
            }
            __syncthreads();
            acc_chunk(s_h1, P.ne1_w + ch * 4096, acc0, acc1, r0, c0);
            __syncthreads();
        }
#pragma unroll
        for (int j = 0; j < 4; j++) {
            s_ya[r0 * 64 + c0 + j] = fmaxf(acc0[j], 0.f);
            s_ya[(r0 + 1) * 64 + c0 + j] = fmaxf(acc1[j], 0.f);
        }
    }
    __syncthreads();
    layer32x64<64, false, true>(s_ya, P.ne2_w, P.ne2_b, s_h1, tid);
    __syncthreads();
    layer_small(s_h1, 64, P.ne3_w, P.ne3_b, s_h2, 32, true, tid);
    __syncthreads();
    layer_small(s_h2, 32, P.ne4_w, P.ne4_b, s_h1, 32, false, tid);  // z_impl
    __syncthreads();

    // zc = concat(z[b,-1], z_impl); restage w2/w3 with le weights
    const float* zlast = zb + 15 * 32 * 32;
    for (int idx = tid; idx < 2048; idx += NT) {
        int o = idx >> 6, c = idx & 63;
        s_zc[idx] = (c < 32) ? zlast[o * 32 + c] : s_h1[o * 32 + (c - 32)];
    }
    for (int idx = tid; idx < 4096; idx += NT) {
        s_w2[idx] = P.le2_w[idx];
        s_w3[idx] = P.le3_w[idx];
    }
    __syncthreads();

    // ---- rollout ----
    float* outb = P.out + (size_t)b * (P.t_future * 32 * 32);
#pragma unroll 1
    for (int t = 0; t < P.t_future; t++) {
        layer32x64<64, false, false>(s_zc, P.le1_w,           nullptr, s_ya, tid);
        layer32x64<64, false, false>(s_zc, P.le1_w + 64 * 64, nullptr, s_yb, tid);
        __syncthreads();
        edge_block(s_ya, s_yb, P.le1_b, s_w2, P.le2_b, s_w3, P.le3_b,
                   s_h1, s_h2, s_yb, s_agg, s_ii, s_jj, s_jl, tid);

        layer32x64<64, false, false>(s_zc,  P.lt1_w,           P.lt1_b, s_h1, tid);
        layer32x64<64, true,  true >(s_agg, P.lt1_w + 64 * 64, nullptr, s_h1, tid);
        __syncthreads();
        layer32x64<64, false, true>(s_h1, P.lt2_w, P.lt2_b, s_h2, tid);
        __syncthreads();
        layer_small(s_h2, 64, P.lt3_w, P.lt3_b, s_h1, 32, true, tid);
        __syncthreads();
        layer_small(s_h1, 32, P.lt4_w, P.lt4_b, s_h2, 16, true, tid);
        __syncthreads();
        layer32x64<16, false, false>(s_h2, P.lt5_w, P.lt5_b, s_h1, tid);  // delta
        __syncthreads();

        for (int idx = tid; idx < 2048; idx += NT) {
            float zn = s_zc[idx] + s_h1[idx];
            s_zc[idx] = zn;
            int o = idx >> 6, c = idx & 63;
            if (c < 32) outb[t * 1024 + o * 32 + c] = zn;
        }
        __syncthreads();
    }
}

extern "C" void kernel_launch(void* const* d_in, const int* in_sizes, int n_in,
                              void* d_out, int out_size)
{
    Params P;
    int i = 0;
    P.z     = (const float*)d_in[i++];
    P.ee1_w = (const float*)d_in[i++]; P.ee1_b = (const float*)d_in[i++];
    P.ee2_w = (const float*)d_in[i++]; P.ee2_b = (const float*)d_in[i++];
    P.ee3_w = (const float*)d_in[i++]; P.ee3_b = (const float*)d_in[i++];
    P.ne1_w = (const float*)d_in[i++]; P.ne1_b = (const float*)d_in[i++];
    P.ne2_w = (const float*)d_in[i++]; P.ne2_b = (const float*)d_in[i++];
    P.ne3_w = (const float*)d_in[i++]; P.ne3_b = (const float*)d_in[i++];
    P.ne4_w = (const float*)d_in[i++]; P.ne4_b = (const float*)d_in[i++];
    P.le1_w = (const float*)d_in[i++]; P.le1_b = (const float*)d_in[i++];
    P.le2_w = (const float*)d_in[i++]; P.le2_b = (const float*)d_in[i++];
    P.le3_w = (const float*)d_in[i++]; P.le3_b = (const float*)d_in[i++];
    P.lt1_w = (const float*)d_in[i++]; P.lt1_b = (const float*)d_in[i++];
    P.lt2_w = (const float*)d_in[i++]; P.lt2_b = (const float*)d_in[i++];
    P.lt3_w = (const float*)d_in[i++]; P.lt3_b = (const float*)d_in[i++];
    P.lt4_w = (const float*)d_in[i++]; P.lt4_b = (const float*)d_in[i++];
    P.lt5_w = (const float*)d_in[i++]; P.lt5_b = (const float*)d_in[i++];
    P.out = (float*)d_out;
    P.t_future = out_size / (256 * 32 * 32);

    cudaFuncSetAttribute(RelationalLatentDynamics_82849919140105_kernel,
                         cudaFuncAttributeMaxDynamicSharedMemorySize, SMEM_BYTES);
    RelationalLatentDynamics_82849919140105_kernel<<<256, NT, SMEM_BYTES>>>(P);
}